// round 17
// baseline (speedup 1.0000x reference)
#include <cuda_runtime.h>
#include <cstdint>

// HexPool: out[i, :] = max_{k<7} x[neigh_indices[i,k], :]
// x: (655362, 64) f32 ; neigh_indices: (163842, 7) int32 ; out: (163842, 64) f32
//
// FINAL kernel (R7; best measured 22.1us, noise band 22.1-23.3us across
// 10 measured variants / 4 re-benches).
//  - 16 threads (one half-warp) per output row, one float4 (LDG.128) per
//    thread: each gather warp-instruction touches only 2 distinct rows ->
//    minimal L1tex wavefronts. Variants that changed this (8 t/row, LDG.256)
//    lost 1-3us; variants that kept it but added MLP/amortization (2 rows
//    per thread) were neutral -- the SM side is not the limiter.
//  - Index broadcast: lanes sub<7 load, one 32-bit SHFL per k; all lanes
//    converged (tail clamps row, predicates only the store).
//  - Output stores __stcs (streaming/evict-first): L2 coalesces dirty lines
//    without retaining them, keeping the 42MB x gather region L2-resident.
//    -10% vs default; __stwt and createpolicy-evict_last both regressed.
// Bottleneck: ~340MB/launch through L2 (294MB uniform-random gather is
// algorithmically irreducible + 42MB output + 4.6MB idx) at ~14-15TB/s
// effective L2-hit bandwidth => ~22us transport floor. DRAM at compulsory
// ~55MB/replay; compute pipes <6%; per-SM L1 gather hit rate <1% by design
// of the access pattern (33MB aggregate L1 vs uniformly-hit 42MB hot set).

#define N_OUT 163842
#define KNB   7
#define VEC_PER_ROW 16   // 64 floats / 4

__global__ __launch_bounds__(256) void hexpool_kernel(
    const float4* __restrict__ x,          // viewed as [n_in][16] float4
    const int* __restrict__ idx,           // [N_OUT][7] int32
    float4* __restrict__ out)               // [N_OUT][16] float4
{
    const int gid = blockIdx.x * blockDim.x + threadIdx.x;
    const int row_raw = gid >> 4;                 // output row (may overshoot in tail)
    const int row = row_raw < N_OUT ? row_raw : (N_OUT - 1);
    const int col = gid & 15;                     // float4 column within row

    const int lane = threadIdx.x & 31;
    const int half_base = lane & 16;              // 0 or 16: start lane of my half-warp
    const int sub = lane & 15;

    // Lanes sub<7 of each half-warp load the 7 indices for this half-warp's row.
    int my_idx = 0;
    if (sub < KNB) {
        my_idx = __ldg(&idx[row * KNB + sub]);
    }

    float4 m = make_float4(-3.402823466e+38f, -3.402823466e+38f,
                           -3.402823466e+38f, -3.402823466e+38f);

    #pragma unroll
    for (int k = 0; k < KNB; ++k) {
        int j = __shfl_sync(0xFFFFFFFFu, my_idx, half_base + k);
        float4 v = __ldg(&x[(long long)j * VEC_PER_ROW + col]);
        m.x = fmaxf(m.x, v.x);
        m.y = fmaxf(m.y, v.y);
        m.z = fmaxf(m.z, v.z);
        m.w = fmaxf(m.w, v.w);
    }

    if (row_raw < N_OUT) {
        __stcs(&out[gid], m);   // streaming: coalesce in L2, evict-first
    }
}

extern "C" void kernel_launch(void* const* d_in, const int* in_sizes, int n_in,
                              void* d_out, int out_size)
{
    const float4* x   = (const float4*)d_in[0];
    const int*    idx = (const int*)d_in[1];
    float4*       out = (float4*)d_out;

    const int total_threads = N_OUT * VEC_PER_ROW;   // 2,621,472
    const int block = 256;
    const int grid  = (total_threads + block - 1) / block;
    hexpool_kernel<<<grid, block>>>(x, idx, out);
}